// round 1
// baseline (speedup 1.0000x reference)
#include <cuda_runtime.h>
#include <cuda_bf16.h>

// FPN RoIAlign, torchvision-style (aligned=false), multi-level.
// Inputs (metadata order): p2[2,256,256,256] p3[2,128,128,256] p4[2,64,64,256]
//                          p5[2,32,32,256]   p6[2,16,16,256]   proposals[2,512,4]
// Output: [2, 512, 7, 7, 256] float32.

#define NB 2
#define NR 512
#define NC 256

__global__ __launch_bounds__(256, 8) void roi_align_fpn(
    const float* __restrict__ p2, const float* __restrict__ p3,
    const float* __restrict__ p4, const float* __restrict__ p5,
    const float* __restrict__ p6, const float* __restrict__ props,
    float* __restrict__ out)
{
    const int br = blockIdx.x;          // b*512 + r
    const int b  = br >> 9;
    const int by = blockIdx.y;          // output bin row 0..6
    const int c  = threadIdx.x;         // channel 0..255

    // ---- proposal & level selection (all threads redundantly; ~50 flops) ----
    const float x1 = props[4 * br + 0];
    const float y1 = props[4 * br + 1];
    const float x2 = props[4 * br + 2];
    const float y2 = props[4 * br + 3];

    const float w = fmaxf(x2 - x1, 1.0f);
    const float h = fmaxf(y2 - y1, 1.0f);
    const float s = sqrtf(w * h);
    // lvl = clip(floor(4 + log2(s/224)), 2, 6)  ==  exact threshold form:
    int lvl = 2;
    if (s >= 112.0f) lvl++;
    if (s >= 224.0f) lvl++;
    if (s >= 448.0f) lvl++;
    if (s >= 896.0f) lvl++;

    const float* feat =
        (lvl == 2) ? p2 : (lvl == 3) ? p3 : (lvl == 4) ? p4 : (lvl == 5) ? p5 : p6;
    const int   hw    = 1024 >> lvl;
    const float scale = 1.0f / (float)(1 << lvl);
    feat += (size_t)b * hw * hw * NC;

    // ---- RoIAlign geometry in feature coords ----
    const float bx1 = x1 * scale, bx2 = x2 * scale;
    const float fy1 = y1 * scale, fy2 = y2 * scale;
    const float roi_w = fmaxf(bx2 - bx1, 1.0f);
    const float roi_h = fmaxf(fy2 - fy1, 1.0f);
    const float bin_w = roi_w * (1.0f / 7.0f);
    const float bin_h = roi_h * (1.0f / 7.0f);
    const float Hf = (float)hw;

    // y subsample pair for this bin row (shared by all 7 x-bins)
    int   y0i[2], y1i[2];
    float wy0[2], wy1[2];
    bool  vy[2];
#pragma unroll
    for (int j = 0; j < 2; j++) {
        const float Y = fy1 + ((float)by + (j + 0.5f) * 0.5f) * bin_h;
        vy[j] = (Y >= -1.0f) && (Y <= Hf);
        const float yc = fminf(fmaxf(Y, 0.0f), Hf - 1.0f);
        const float y0 = floorf(yc);
        y0i[j] = (int)y0;
        y1i[j] = min(y0i[j] + 1, hw - 1);
        const float ly = yc - y0;
        wy1[j] = ly;
        wy0[j] = 1.0f - ly;
    }

    const size_t row0 = (size_t)y0i[0] * hw * NC;
    const size_t row1 = (size_t)y1i[0] * hw * NC;
    const size_t row2 = (size_t)y0i[1] * hw * NC;
    const size_t row3 = (size_t)y1i[1] * hw * NC;

    size_t out_base = ((size_t)br * 49 + (size_t)by * 7) * NC + c;

    for (int ox = 0; ox < 7; ox++) {
        float acc = 0.0f;
#pragma unroll
        for (int i = 0; i < 2; i++) {
            const float X = bx1 + ((float)ox + (i + 0.5f) * 0.5f) * bin_w;
            const bool  vx = (X >= -1.0f) && (X <= Hf);
            const float xc = fminf(fmaxf(X, 0.0f), Hf - 1.0f);
            const float x0 = floorf(xc);
            const int   x0i = (int)x0;
            const int   x1i = min(x0i + 1, hw - 1);
            const float lx = xc - x0;
            const float hx = 1.0f - lx;
            const size_t c0 = (size_t)x0i * NC + c;
            const size_t c1 = (size_t)x1i * NC + c;

            if (vx && vy[0]) {
                const float v00 = __ldg(feat + row0 + c0);
                const float v01 = __ldg(feat + row0 + c1);
                const float v10 = __ldg(feat + row1 + c0);
                const float v11 = __ldg(feat + row1 + c1);
                acc += wy0[0] * (hx * v00 + lx * v01)
                     + wy1[0] * (hx * v10 + lx * v11);
            }
            if (vx && vy[1]) {
                const float v00 = __ldg(feat + row2 + c0);
                const float v01 = __ldg(feat + row2 + c1);
                const float v10 = __ldg(feat + row3 + c0);
                const float v11 = __ldg(feat + row3 + c1);
                acc += wy0[1] * (hx * v00 + lx * v01)
                     + wy1[1] * (hx * v10 + lx * v11);
            }
        }
        out[out_base + (size_t)ox * NC] = acc * 0.25f;
    }
}

extern "C" void kernel_launch(void* const* d_in, const int* in_sizes, int n_in,
                              void* d_out, int out_size)
{
    const float* p2 = (const float*)d_in[0];
    const float* p3 = (const float*)d_in[1];
    const float* p4 = (const float*)d_in[2];
    const float* p5 = (const float*)d_in[3];
    const float* p6 = (const float*)d_in[4];
    const float* pr = (const float*)d_in[5];
    float* out = (float*)d_out;

    dim3 grid(NB * NR, 7);
    roi_align_fpn<<<grid, NC>>>(p2, p3, p4, p5, p6, pr, out);
}

// round 4
// speedup vs baseline: 1.7866x; 1.7866x over previous
#include <cuda_runtime.h>
#include <cuda_bf16.h>

// FPN RoIAlign, torchvision-style (aligned=false), multi-level.
// Inputs (metadata order): p2[2,256,256,256] p3[2,128,128,256] p4[2,64,64,256]
//                          p5[2,32,32,256]   p6[2,16,16,256]   proposals[2,512,4]
// Output: [2, 512, 7, 7, 256] float32.
//
// Layout: grid = (1024 rois, 7 bin-rows), block = (64 float4-channel-groups, 7 x-bins).
// Each thread produces one float4 of one output bin: 16x LDG.128, ~70 FMA, 1x STG.128.
// All offset arithmetic in 32-bit float4 units (max 2*256*256*64 = 8.4M < 2^31).

#define NB 2
#define NR 512
#define NCG 64   // 256 channels / 4

__global__ __launch_bounds__(448) void roi_align_fpn(
    const float4* __restrict__ p2, const float4* __restrict__ p3,
    const float4* __restrict__ p4, const float4* __restrict__ p5,
    const float4* __restrict__ p6, const float* __restrict__ props,
    float4* __restrict__ out)
{
    const int br = blockIdx.x;          // b*512 + r
    const int by = blockIdx.y;          // output bin row 0..6
    const int ox = threadIdx.y;         // output bin col 0..6
    const int cg = threadIdx.x;         // channel group 0..63 (4 floats each)

    // ---- proposal & level selection ----
    const float x1 = props[4 * br + 0];
    const float y1 = props[4 * br + 1];
    const float x2 = props[4 * br + 2];
    const float y2 = props[4 * br + 3];

    const float w = fmaxf(x2 - x1, 1.0f);
    const float h = fmaxf(y2 - y1, 1.0f);
    const float s = sqrtf(w * h);
    // lvl = clip(floor(4 + log2(s/224)), 2, 6) == exact threshold form
    int lvl = 2;
    if (s >= 112.0f) lvl++;
    if (s >= 224.0f) lvl++;
    if (s >= 448.0f) lvl++;
    if (s >= 896.0f) lvl++;

    const float4* feat =
        (lvl == 2) ? p2 : (lvl == 3) ? p3 : (lvl == 4) ? p4 : (lvl == 5) ? p5 : p6;
    const int   hw    = 1024 >> lvl;
    const float scale = 1.0f / (float)(1 << lvl);
    const int   rowstride = hw * NCG;              // float4 units per feature row
    feat += (br >> 9) * hw * rowstride;            // batch offset

    // ---- RoIAlign geometry (feature coords) ----
    const float bx1 = x1 * scale;
    const float fy1 = y1 * scale;
    const float roi_w = fmaxf(x2 * scale - bx1, 1.0f);
    const float roi_h = fmaxf(y2 * scale - fy1, 1.0f);
    const float bin_w = roi_w * (1.0f / 7.0f);
    const float bin_h = roi_h * (1.0f / 7.0f);
    const float Hf = (float)hw;

    // y subsample pair for this bin row
    int   rofs[2][2];     // [j][0..1] row offsets (float4 units)
    float wy[2][2];       // [j][hy, ly]
#pragma unroll
    for (int j = 0; j < 2; j++) {
        const float Y = fy1 + ((float)by + (j ? 0.75f : 0.25f)) * bin_h;
        const bool vyj = (Y >= -1.0f) && (Y <= Hf);
        const float yc = fminf(fmaxf(Y, 0.0f), Hf - 1.0f);
        const float y0 = floorf(yc);
        const int y0i = (int)y0;
        const int y1i = min(y0i + 1, hw - 1);
        rofs[j][0] = y0i * rowstride;
        rofs[j][1] = y1i * rowstride;
        const float ly = yc - y0;
        // fold y-validity into the weights: invalid subsample contributes 0
        wy[j][0] = vyj ? (1.0f - ly) : 0.0f;
        wy[j][1] = vyj ? ly : 0.0f;
    }

    float4 acc = make_float4(0.f, 0.f, 0.f, 0.f);

#pragma unroll
    for (int i = 0; i < 2; i++) {
        const float X = bx1 + ((float)ox + (i ? 0.75f : 0.25f)) * bin_w;
        const bool vx = (X >= -1.0f) && (X <= Hf);
        const float xc = fminf(fmaxf(X, 0.0f), Hf - 1.0f);
        const float x0 = floorf(xc);
        const int x0i = (int)x0;
        const int x1i = min(x0i + 1, hw - 1);
        const float lx0 = xc - x0;
        const float lx = vx ? lx0 : 0.0f;          // fold x-validity into weights
        const float hx = vx ? (1.0f - lx0) : 0.0f;
        const int c0 = x0i * NCG + cg;
        const int c1 = x1i * NCG + cg;

#pragma unroll
        for (int j = 0; j < 2; j++) {
            const float w00 = wy[j][0] * hx;
            const float w01 = wy[j][0] * lx;
            const float w10 = wy[j][1] * hx;
            const float w11 = wy[j][1] * lx;
            const float4 v00 = __ldg(feat + rofs[j][0] + c0);
            const float4 v01 = __ldg(feat + rofs[j][0] + c1);
            const float4 v10 = __ldg(feat + rofs[j][1] + c0);
            const float4 v11 = __ldg(feat + rofs[j][1] + c1);
            acc.x += w00 * v00.x + w01 * v01.x + w10 * v10.x + w11 * v11.x;
            acc.y += w00 * v00.y + w01 * v01.y + w10 * v10.y + w11 * v11.y;
            acc.z += w00 * v00.z + w01 * v01.z + w10 * v10.z + w11 * v11.z;
            acc.w += w00 * v00.w + w01 * v01.w + w10 * v10.w + w11 * v11.w;
        }
    }

    acc.x *= 0.25f; acc.y *= 0.25f; acc.z *= 0.25f; acc.w *= 0.25f;
    out[((br * 49 + by * 7 + ox) * NCG) + cg] = acc;
}

extern "C" void kernel_launch(void* const* d_in, const int* in_sizes, int n_in,
                              void* d_out, int out_size)
{
    const float4* p2 = (const float4*)d_in[0];
    const float4* p3 = (const float4*)d_in[1];
    const float4* p4 = (const float4*)d_in[2];
    const float4* p5 = (const float4*)d_in[3];
    const float4* p6 = (const float4*)d_in[4];
    const float*  pr = (const float*)d_in[5];
    float4* out = (float4*)d_out;

    dim3 grid(NB * NR, 7);
    dim3 block(NCG, 7);
    roi_align_fpn<<<grid, block>>>(p2, p3, p4, p5, p6, pr, out);
}